// round 7
// baseline (speedup 1.0000x reference)
#include <cuda_runtime.h>

// CritiGraph_64175401337324 — fused kernel v3:
//  persistent 2-t CTAs: grid 512 (single resident wave, no tail),
//  body identical to validated R6 (factored loss, merged butterfly).

namespace {
constexpr int T_   = 1024;
constexpr int S_   = 64;
constexpr int D_   = 256;
constexpr int TP_  = 8;
constexpr int C_   = 65;
constexpr int CUR_TP_ = 4;
constexpr int GRID_ = 512;               // 2 t per CTA
}

__device__ int g_is64;

__global__ void detect_dtype_kernel(const void* p0) {
    // int64 values in [-131071,131071] => high half == sign-ext of low half
    const long long* p = (const long long*)p0;
    int ok = 1;
    for (int i = 0; i < 64; ++i) {
        long long v = p[i];
        int lo = (int)v, hi = (int)(v >> 32);
        if (hi != (lo < 0 ? -1 : 0)) { ok = 0; break; }
    }
    g_is64 = ok;
}

// pack |v| with sign in bit 31
__device__ __forceinline__ unsigned enc_loc(int v) {
    unsigned a = (unsigned)(v < 0 ? -v : v);
    if (v < 0) a |= 0x80000000u;
    return a;
}

// sign * (16 - e), e = frexp-exponent of ((|a|^|b|)+1). Exact in fp32.
__device__ __forceinline__ float cos_core(unsigned ea, unsigned eb) {
    unsigned u = ea ^ eb;
    int e = 32 - __clz((int)((u & 0x7FFFFFFFu) + 1u));
    float f = (float)(16 - e);
    return (u & 0x80000000u) ? -f : f;
}

__global__ void __launch_bounds__(256, 5) fused_kernel(
    const void*  __restrict__ sta_loc,
    const void*  __restrict__ nei_loc,
    const void*  __restrict__ rand_numbers,
    const float* __restrict__ sta_emb,
    const float* __restrict__ nei_emb,
    const float* __restrict__ mask,
    const float* __restrict__ rand_vals,
    const float* __restrict__ t_rand,
    float* __restrict__ out)
{
    const int tid  = threadIdx.x;
    const int lane = tid & 31;
    const int warp = tid >> 5;
    const int is64 = g_is64;
    const int p_ = tid & 7;
    const int j_ = tid >> 3;

    __shared__ __align__(16) float    s_eu[S_];
    __shared__ __align__(16) float    s_w[S_];          // |eu|*mask*invlth
    __shared__ __align__(16) float    s_m[S_];
    __shared__ __align__(16) float    s_csT[TP_][68];   // cos_sn, transposed
    __shared__ __align__(16) unsigned s_nlT[TP_][68];   // enc(nei), transposed
    __shared__ __align__(16) float    s_G[TP_][68];     // 2*w*B
    __shared__ float    s_WB2[TP_];                     // sum w*B^2
    __shared__ int      s_clv[C_ * TP_];
    __shared__ float    s_loss[C_ * TP_];
    __shared__ float    s_p32[4][TP_];
    __shared__ float    s_rv[TP_], s_rl[TP_];
    __shared__ float    s_red[2];
    __shared__ int      s_sel;

    #pragma unroll 1
    for (int tt = 0; tt < 2; ++tt) {
        const int t = blockIdx.x + (tt << 9);

        // ---- issue nei batch-1 loads first ----
        const float4* st4 = (const float4*)(sta_emb + (size_t)t * D_);
        const float4  ua  = st4[lane];
        const float4  ub  = st4[lane + 32];
        const float4* nb  = (const float4*)(nei_emb + ((size_t)(t * S_ + warp * 8)) * D_);

        float4 A[4], Bv[4];
        #pragma unroll
        for (int r = 0; r < 4; ++r) {
            A[r]  = nb[r * 64 + lane];
            Bv[r] = nb[r * 64 + lane + 32];
        }

        // ---- integer loads + encode (overlapped with nei latency) ----
        int nl0, nl1, rn, orip;
        if (is64) {
            const long long* NL = (const long long*)nei_loc + (size_t)t * (S_ * TP_);
            nl0  = (int)NL[tid];
            nl1  = (int)NL[tid + 256];
            rn   = (int)((const long long*)rand_numbers)[t * 256 + tid];
            orip = (int)((const long long*)sta_loc)[t * TP_ + p_];
        } else {
            const int* NL = (const int*)nei_loc + t * (S_ * TP_);
            nl0  = NL[tid];
            nl1  = NL[tid + 256];
            rn   = ((const int*)rand_numbers)[t * 256 + tid];
            orip = ((const int*)sta_loc)[t * TP_ + p_];
        }
        float m = 0.f;
        if (tid < S_) { m = mask[t * S_ + tid]; s_m[tid] = m; }
        if (tid < TP_) {
            s_rv[tid] = rand_vals[t * TP_ + tid];
            s_clv[32 * TP_ + tid] = orip;     // p_ == tid here
        }
        if (tid == 0) s_sel = (t_rand[t] < 0.8f) ? 1 : 0;

        {   // encodings + cos_sn (exact multiples of 1/16)
            const unsigned op = enc_loc(orip);
            unsigned ne0 = enc_loc(nl0);
            unsigned ne1 = enc_loc(nl1);
            s_nlT[p_][j_]      = ne0;
            s_nlT[p_][j_ + 32] = ne1;
            s_csT[p_][j_]      = cos_core(op, ne0) * 0.0625f;
            s_csT[p_][j_ + 32] = cos_core(op, ne1) * 0.0625f;
        }
        int vcand;
        {
            const int h = j_ >> 1;
            vcand = (orip ^ (1 << h)) ^ (rn & ((1 << h) - 1));
            s_clv[j_ * TP_ + p_]        = vcand;
            s_clv[(j_ + 33) * TP_ + p_] = -vcand;
        }
        // lth partial reduce (mask is 0/1: exact in any order)
        if (tid < S_) {
            float l = m;
            #pragma unroll
            for (int off = 16; off; off >>= 1) l += __shfl_xor_sync(0xFFFFFFFFu, l, off);
            if (lane == 0) s_red[warp] = l;
        }

        // ---- eu: FFMA batch-1, load batch-2, FFMA batch-2 ----
        float dot[8], nn[8];
        #pragma unroll
        for (int r = 0; r < 4; ++r) {
            dot[r] = A[r].x*ua.x + A[r].y*ua.y + A[r].z*ua.z + A[r].w*ua.w
                   + Bv[r].x*ub.x + Bv[r].y*ub.y + Bv[r].z*ub.z + Bv[r].w*ub.w;
            nn[r]  = A[r].x*A[r].x + A[r].y*A[r].y + A[r].z*A[r].z + A[r].w*A[r].w
                   + Bv[r].x*Bv[r].x + Bv[r].y*Bv[r].y + Bv[r].z*Bv[r].z + Bv[r].w*Bv[r].w;
        }
        #pragma unroll
        for (int r = 0; r < 4; ++r) {
            A[r]  = nb[(4 + r) * 64 + lane];
            Bv[r] = nb[(4 + r) * 64 + lane + 32];
        }
        #pragma unroll
        for (int r = 0; r < 4; ++r) {
            dot[4+r] = A[r].x*ua.x + A[r].y*ua.y + A[r].z*ua.z + A[r].w*ua.w
                     + Bv[r].x*ub.x + Bv[r].y*ub.y + Bv[r].z*ub.z + Bv[r].w*ub.w;
            nn[4+r]  = A[r].x*A[r].x + A[r].y*A[r].y + A[r].z*A[r].z + A[r].w*A[r].w
                     + Bv[r].x*Bv[r].x + Bv[r].y*Bv[r].y + Bv[r].z*Bv[r].z + Bv[r].w*Bv[r].w;
        }
        float ss = ua.x*ua.x + ua.y*ua.y + ua.z*ua.z + ua.w*ua.w
                 + ub.x*ub.x + ub.y*ub.y + ub.z*ub.z + ub.w*ub.w;

        // ---- merged butterfly: 16 values in 31 shuffles (same FP tree) ----
        {
            float r16[16];
            #pragma unroll
            for (int i = 0; i < 8; ++i) { r16[i] = dot[i]; r16[8+i] = nn[i]; }
            float t0[16];
            #pragma unroll
            for (int i = 0; i < 16; ++i)
                t0[i] = r16[i] + __shfl_xor_sync(0xFFFFFFFFu, r16[i], 16);
            float m8[8];
            #pragma unroll
            for (int k = 0; k < 8; ++k) m8[k] = (lane & 16) ? t0[k+8] : t0[k];
            float u4[8];
            #pragma unroll
            for (int k = 0; k < 8; ++k)
                u4[k] = m8[k] + __shfl_xor_sync(0xFFFFFFFFu, m8[k], 8);
            float q[4];
            #pragma unroll
            for (int k = 0; k < 4; ++k) q[k] = (lane & 8) ? u4[k+4] : u4[k];
            float v4[4];
            #pragma unroll
            for (int k = 0; k < 4; ++k)
                v4[k] = q[k] + __shfl_xor_sync(0xFFFFFFFFu, q[k], 4);
            float w0 = (lane & 4) ? v4[2] : v4[0];
            float w1 = (lane & 4) ? v4[3] : v4[1];
            float x0 = w0 + __shfl_xor_sync(0xFFFFFFFFu, w0, 2);
            float x1 = w1 + __shfl_xor_sync(0xFFFFFFFFu, w1, 2);
            float y  = (lane & 2) ? x1 : x0;
            float z  = y + __shfl_xor_sync(0xFFFFFFFFu, y, 1);
            #pragma unroll
            for (int off = 16; off; off >>= 1) ss += __shfl_xor_sync(0xFFFFFFFFu, ss, off);
            float nnv = __shfl_xor_sync(0xFFFFFFFFu, z, 16);   // nn of same row
            if (lane < 16 && !(lane & 1)) {
                int row = lane >> 1;
                s_eu[warp * 8 + row] = z / (sqrtf(ss) * sqrtf(nnv));
            }
        }
        __syncthreads();                 // s_eu, s_red, s_csT, s_nlT, s_m ready

        // ---- B-phase: warp = p, lanes cover s and s+32 ----
        {
            const float invlth = __frcp_rn(s_red[0] + s_red[1] + 1e-12f);
            const int p = warp, s0 = lane, s1 = lane + 32;
            float sum0 = 0.f, sum1 = 0.f;
            #pragma unroll
            for (int pp = 0; pp < TP_; ++pp) { sum0 += s_csT[pp][s0]; sum1 += s_csT[pp][s1]; }
            float cs0 = s_csT[p][s0], cs1 = s_csT[p][s1];
            float eu0 = s_eu[s0],     eu1 = s_eu[s1];
            float B0 = (sum0 - cs0) * 0.125f - eu0;
            float B1 = (sum1 - cs1) * 0.125f - eu1;
            float w0 = fabsf(eu0) * s_m[s0] * invlth;
            float w1 = fabsf(eu1) * s_m[s1] * invlth;
            float q0 = w0 * B0, q1 = w1 * B1;
            s_G[p][s0] = q0 + q0;                          // 2wB (exact x2)
            s_G[p][s1] = q1 + q1;
            if (p == 0) { s_w[s0] = w0; s_w[s1] = w1; }
            float wb2 = __fmaf_rn(q1, B1, q0 * B0);
            #pragma unroll
            for (int off = 16; off; off >>= 1) wb2 += __shfl_xor_sync(0xFFFFFFFFu, wb2, off);
            if (lane == 0) s_WB2[p] = wb2;
        }
        __syncthreads();

        // ---- phase 4: pair (j, j+33); t2 shared, t1 sign-flips exactly ----
        {
            const int p = p_, j = j_;
            const unsigned e0 = enc_loc(vcand);
            const unsigned flip = e0 ? 0x80000000u : 0u;

            const uint4*  neP = (const uint4*) &s_nlT[p][0];
            const float4* GP  = (const float4*)&s_G[p][0];
            const float4* wP  = (const float4*)s_w;

            float t1 = 0.f, t2 = 0.f;

#define PROC(NE, G, W) do {                                                   \
            unsigned u  = e0 ^ (NE);                                          \
            unsigned x2 = u * 2u + 2u;                                        \
            float cf = (float)__clz((int)x2);                                 \
            float mg = __fmaf_rn(cf, 0.0078125f, -0.1171875f);                \
            float sG = __uint_as_float(__float_as_uint(G) ^ (u & 0x80000000u));\
            t1 = __fmaf_rn(mg, sG, t1);                                       \
            t2 = __fmaf_rn(__fmul_rn(mg, mg), (W), t2);                       \
        } while (0)

            #pragma unroll 4
            for (int g = 0; g < 16; ++g) {
                uint4  n4 = neP[g];
                float4 G4 = GP[g];
                float4 W4 = wP[g];
                PROC(n4.x, G4.x, W4.x);
                PROC(n4.y, G4.y, W4.y);
                PROC(n4.z, G4.z, W4.z);
                PROC(n4.w, G4.w, W4.w);
            }
#undef PROC

            float base = s_WB2[p] + t2;
            s_loss[j * TP_ + p]        = base + t1;
            s_loss[(j + 33) * TP_ + p] = base + __uint_as_float(__float_as_uint(t1) ^ flip);
        }
        // candidate 32 (= ori): v = cos_sn/8, same factored form
        if (warp == 7) {
            const int p = lane & 7, chunk = lane >> 3;
            const int sb = chunk * 16;
            float t1 = 0.f, t2 = 0.f;
            #pragma unroll
            for (int s = sb; s < sb + 16; ++s) {
                float v = s_csT[p][s] * 0.125f;
                t1 = __fmaf_rn(v, s_G[p][s], t1);
                t2 = __fmaf_rn(__fmul_rn(v, v), s_w[s], t2);
            }
            s_p32[chunk][p] = t1 + t2;
        }
        __syncthreads();

        // ---- phase 5: warp p argmin over 65 (lexicographic shuffle-min) ----
        {
            const int p = warp;
            float va = s_loss[lane * TP_ + p];
            float vb = s_loss[(lane + 33) * TP_ + p];
            float v = va; int ci = lane;
            if (vb < v) { v = vb; ci = lane + 33; }
            if (lane == 0) {
                float v32 = s_WB2[p] +
                    ((((s_p32[0][p] + s_p32[1][p]) + s_p32[2][p]) + s_p32[3][p]));
                s_loss[32 * TP_ + p] = v32;
                if (v32 < v || (v32 == v && 32 < ci)) { v = v32; ci = 32; }
            }
            #pragma unroll
            for (int off = 16; off; off >>= 1) {
                float v2 = __shfl_xor_sync(0xFFFFFFFFu, v, off);
                int   c2 = __shfl_xor_sync(0xFFFFFFFFu, ci, off);
                if (v2 < v || (v2 == v && c2 < ci)) { v = v2; ci = c2; }
            }
            if (lane == 0) {
                float rp = s_rv[p];
                int rank = 0;
                #pragma unroll
                for (int q = 0; q < TP_; ++q)
                    rank += (s_rv[q] < rp) || (s_rv[q] == rp && q < p);
                int idx = (rank < CUR_TP_ && s_sel) ? ci : 32;
                out[t * TP_ + p] = (float)s_clv[idx * TP_ + p];
                s_rl[p] = s_loss[idx * TP_ + p];
            }
        }
        __syncthreads();
        if (tid == 0) {
            float rl = 0.f;
            #pragma unroll
            for (int p = 0; p < TP_; ++p) rl = __fadd_rn(rl, s_rl[p]);
            out[T_ * TP_ + t] = rl * 0.125f;
        }
        __syncthreads();                 // protect shared reuse across t's
    }
}

extern "C" void kernel_launch(void* const* d_in, const int* in_sizes, int n_in,
                              void* d_out, int out_size) {
    (void)in_sizes; (void)n_in; (void)out_size;
    detect_dtype_kernel<<<1, 1>>>(d_in[0]);
    fused_kernel<<<GRID_, 256>>>(
        d_in[0], d_in[1], d_in[2],
        (const float*)d_in[3], (const float*)d_in[4], (const float*)d_in[5],
        (const float*)d_in[6], (const float*)d_in[7],
        (float*)d_out);
}

// round 8
// speedup vs baseline: 1.1811x; 1.1811x over previous
#include <cuda_runtime.h>

// CritiGraph_64175401337324 — fused kernel v4:
//  = validated R6 body (grid 1024, factored loss, merged butterfly)
//  + __launch_bounds__(256, 6): 42 regs -> 6 CTAs/SM occupancy ceiling.

namespace {
constexpr int T_   = 1024;
constexpr int S_   = 64;
constexpr int D_   = 256;
constexpr int TP_  = 8;
constexpr int C_   = 65;
constexpr int CUR_TP_ = 4;
}

__device__ int g_is64;

__global__ void detect_dtype_kernel(const void* p0) {
    // int64 values in [-131071,131071] => high half == sign-ext of low half
    const long long* p = (const long long*)p0;
    int ok = 1;
    for (int i = 0; i < 64; ++i) {
        long long v = p[i];
        int lo = (int)v, hi = (int)(v >> 32);
        if (hi != (lo < 0 ? -1 : 0)) { ok = 0; break; }
    }
    g_is64 = ok;
}

// pack |v| with sign in bit 31
__device__ __forceinline__ unsigned enc_loc(int v) {
    unsigned a = (unsigned)(v < 0 ? -v : v);
    if (v < 0) a |= 0x80000000u;
    return a;
}

// sign * (16 - e), e = frexp-exponent of ((|a|^|b|)+1). Exact in fp32.
__device__ __forceinline__ float cos_core(unsigned ea, unsigned eb) {
    unsigned u = ea ^ eb;
    int e = 32 - __clz((int)((u & 0x7FFFFFFFu) + 1u));
    float f = (float)(16 - e);
    return (u & 0x80000000u) ? -f : f;
}

__global__ void __launch_bounds__(256, 6) fused_kernel(
    const void*  __restrict__ sta_loc,
    const void*  __restrict__ nei_loc,
    const void*  __restrict__ rand_numbers,
    const float* __restrict__ sta_emb,
    const float* __restrict__ nei_emb,
    const float* __restrict__ mask,
    const float* __restrict__ rand_vals,
    const float* __restrict__ t_rand,
    float* __restrict__ out)
{
    const int t    = blockIdx.x;
    const int tid  = threadIdx.x;
    const int lane = tid & 31;
    const int warp = tid >> 5;
    const int is64 = g_is64;
    const int p_ = tid & 7;
    const int j_ = tid >> 3;

    __shared__ __align__(16) float    s_eu[S_];
    __shared__ __align__(16) float    s_w[S_];          // |eu|*mask*invlth
    __shared__ __align__(16) float    s_m[S_];
    __shared__ __align__(16) float    s_csT[TP_][68];   // cos_sn, transposed
    __shared__ __align__(16) unsigned s_nlT[TP_][68];   // enc(nei), transposed
    __shared__ __align__(16) float    s_G[TP_][68];     // 2*w*B
    __shared__ float    s_WB2[TP_];                     // sum w*B^2
    __shared__ int      s_clv[C_ * TP_];
    __shared__ float    s_loss[C_ * TP_];
    __shared__ float    s_p32[4][TP_];
    __shared__ float    s_rv[TP_], s_rl[TP_];
    __shared__ float    s_red[2];
    __shared__ int      s_sel;

    // ---- issue nei batch-1 loads first (in flight during integer work) ----
    const float4* st4 = (const float4*)(sta_emb + (size_t)t * D_);
    const float4  ua  = st4[lane];
    const float4  ub  = st4[lane + 32];
    const float4* nb  = (const float4*)(nei_emb + ((size_t)(t * S_ + warp * 8)) * D_);

    float4 A[4], Bv[4];
    #pragma unroll
    for (int r = 0; r < 4; ++r) {
        A[r]  = nb[r * 64 + lane];
        Bv[r] = nb[r * 64 + lane + 32];
    }

    // ---- integer loads + encode (overlapped with nei latency) ----
    int nl0, nl1, rn, orip;
    if (is64) {
        const long long* NL = (const long long*)nei_loc + (size_t)t * (S_ * TP_);
        nl0  = (int)NL[tid];
        nl1  = (int)NL[tid + 256];
        rn   = (int)((const long long*)rand_numbers)[t * 256 + tid];
        orip = (int)((const long long*)sta_loc)[t * TP_ + p_];
    } else {
        const int* NL = (const int*)nei_loc + t * (S_ * TP_);
        nl0  = NL[tid];
        nl1  = NL[tid + 256];
        rn   = ((const int*)rand_numbers)[t * 256 + tid];
        orip = ((const int*)sta_loc)[t * TP_ + p_];
    }
    float m = 0.f;
    if (tid < S_) { m = mask[t * S_ + tid]; s_m[tid] = m; }
    if (tid < TP_) {
        s_rv[tid] = rand_vals[t * TP_ + tid];
        s_clv[32 * TP_ + tid] = orip;     // p_ == tid here
    }
    if (tid == 0) s_sel = (t_rand[t] < 0.8f) ? 1 : 0;

    {   // encodings + cos_sn (exact multiples of 1/16)
        const unsigned op = enc_loc(orip);
        unsigned ne0 = enc_loc(nl0);
        unsigned ne1 = enc_loc(nl1);
        s_nlT[p_][j_]      = ne0;
        s_nlT[p_][j_ + 32] = ne1;
        s_csT[p_][j_]      = cos_core(op, ne0) * 0.0625f;
        s_csT[p_][j_ + 32] = cos_core(op, ne1) * 0.0625f;
    }
    int vcand;
    {
        const int h = j_ >> 1;
        vcand = (orip ^ (1 << h)) ^ (rn & ((1 << h) - 1));
        s_clv[j_ * TP_ + p_]        = vcand;
        s_clv[(j_ + 33) * TP_ + p_] = -vcand;
    }
    // lth partial reduce (mask is 0/1: exact in any order)
    if (tid < S_) {
        float l = m;
        #pragma unroll
        for (int off = 16; off; off >>= 1) l += __shfl_xor_sync(0xFFFFFFFFu, l, off);
        if (lane == 0) s_red[warp] = l;
    }

    // ---- eu: FFMA batch-1, load batch-2, FFMA batch-2 ----
    float dot[8], nn[8];
    #pragma unroll
    for (int r = 0; r < 4; ++r) {
        dot[r] = A[r].x*ua.x + A[r].y*ua.y + A[r].z*ua.z + A[r].w*ua.w
               + Bv[r].x*ub.x + Bv[r].y*ub.y + Bv[r].z*ub.z + Bv[r].w*ub.w;
        nn[r]  = A[r].x*A[r].x + A[r].y*A[r].y + A[r].z*A[r].z + A[r].w*A[r].w
               + Bv[r].x*Bv[r].x + Bv[r].y*Bv[r].y + Bv[r].z*Bv[r].z + Bv[r].w*Bv[r].w;
    }
    #pragma unroll
    for (int r = 0; r < 4; ++r) {
        A[r]  = nb[(4 + r) * 64 + lane];
        Bv[r] = nb[(4 + r) * 64 + lane + 32];
    }
    #pragma unroll
    for (int r = 0; r < 4; ++r) {
        dot[4+r] = A[r].x*ua.x + A[r].y*ua.y + A[r].z*ua.z + A[r].w*ua.w
                 + Bv[r].x*ub.x + Bv[r].y*ub.y + Bv[r].z*ub.z + Bv[r].w*ub.w;
        nn[4+r]  = A[r].x*A[r].x + A[r].y*A[r].y + A[r].z*A[r].z + A[r].w*A[r].w
                 + Bv[r].x*Bv[r].x + Bv[r].y*Bv[r].y + Bv[r].z*Bv[r].z + Bv[r].w*Bv[r].w;
    }
    float ss = ua.x*ua.x + ua.y*ua.y + ua.z*ua.z + ua.w*ua.w
             + ub.x*ub.x + ub.y*ub.y + ub.z*ub.z + ub.w*ub.w;

    // ---- merged butterfly: 16 values reduced in 31 shuffles (same FP tree) ----
    {
        float r16[16];
        #pragma unroll
        for (int i = 0; i < 8; ++i) { r16[i] = dot[i]; r16[8+i] = nn[i]; }
        float t0[16];
        #pragma unroll
        for (int i = 0; i < 16; ++i)
            t0[i] = r16[i] + __shfl_xor_sync(0xFFFFFFFFu, r16[i], 16);
        float m8[8];
        #pragma unroll
        for (int k = 0; k < 8; ++k) m8[k] = (lane & 16) ? t0[k+8] : t0[k];
        float u4[8];
        #pragma unroll
        for (int k = 0; k < 8; ++k)
            u4[k] = m8[k] + __shfl_xor_sync(0xFFFFFFFFu, m8[k], 8);
        float q[4];
        #pragma unroll
        for (int k = 0; k < 4; ++k) q[k] = (lane & 8) ? u4[k+4] : u4[k];
        float v4[4];
        #pragma unroll
        for (int k = 0; k < 4; ++k)
            v4[k] = q[k] + __shfl_xor_sync(0xFFFFFFFFu, q[k], 4);
        float w0 = (lane & 4) ? v4[2] : v4[0];
        float w1 = (lane & 4) ? v4[3] : v4[1];
        float x0 = w0 + __shfl_xor_sync(0xFFFFFFFFu, w0, 2);
        float x1 = w1 + __shfl_xor_sync(0xFFFFFFFFu, w1, 2);
        float y  = (lane & 2) ? x1 : x0;
        float z  = y + __shfl_xor_sync(0xFFFFFFFFu, y, 1);
        #pragma unroll
        for (int off = 16; off; off >>= 1) ss += __shfl_xor_sync(0xFFFFFFFFu, ss, off);
        float nnv = __shfl_xor_sync(0xFFFFFFFFu, z, 16);   // nn for same row
        if (lane < 16 && !(lane & 1)) {
            int row = lane >> 1;
            s_eu[warp * 8 + row] = z / (sqrtf(ss) * sqrtf(nnv));
        }
    }
    __syncthreads();                     // s_eu, s_red, s_csT, s_nlT, s_m ready

    // ---- B-phase: warp = p, lanes cover s and s+32 ----
    {
        const float invlth = __frcp_rn(s_red[0] + s_red[1] + 1e-12f);
        const int p = warp, s0 = lane, s1 = lane + 32;
        float sum0 = 0.f, sum1 = 0.f;
        #pragma unroll
        for (int pp = 0; pp < TP_; ++pp) { sum0 += s_csT[pp][s0]; sum1 += s_csT[pp][s1]; }
        float cs0 = s_csT[p][s0], cs1 = s_csT[p][s1];
        float eu0 = s_eu[s0],     eu1 = s_eu[s1];
        float B0 = (sum0 - cs0) * 0.125f - eu0;            // exact A8, 1 rounding
        float B1 = (sum1 - cs1) * 0.125f - eu1;
        float w0 = fabsf(eu0) * s_m[s0] * invlth;
        float w1 = fabsf(eu1) * s_m[s1] * invlth;
        float q0 = w0 * B0, q1 = w1 * B1;
        s_G[p][s0] = q0 + q0;                              // 2wB (exact x2)
        s_G[p][s1] = q1 + q1;
        if (p == 0) { s_w[s0] = w0; s_w[s1] = w1; }
        float wb2 = __fmaf_rn(q1, B1, q0 * B0);
        #pragma unroll
        for (int off = 16; off; off >>= 1) wb2 += __shfl_xor_sync(0xFFFFFFFFu, wb2, off);
        if (lane == 0) s_WB2[p] = wb2;
    }
    __syncthreads();

    // ---- phase 4: pair (j, j+33); t2 shared, t1 sign-flips exactly ----
    {
        const int p = p_, j = j_;
        const unsigned e0 = enc_loc(vcand);
        const unsigned flip = e0 ? 0x80000000u : 0u;

        const uint4*  neP = (const uint4*) &s_nlT[p][0];
        const float4* GP  = (const float4*)&s_G[p][0];
        const float4* wP  = (const float4*)s_w;

        float t1 = 0.f, t2 = 0.f;

#define PROC(NE, G, W) do {                                                   \
        unsigned u  = e0 ^ (NE);                                              \
        unsigned x2 = u * 2u + 2u;                                            \
        float cf = (float)__clz((int)x2);                                     \
        float mg = __fmaf_rn(cf, 0.0078125f, -0.1171875f);                    \
        float sG = __uint_as_float(__float_as_uint(G) ^ (u & 0x80000000u));   \
        t1 = __fmaf_rn(mg, sG, t1);                                           \
        t2 = __fmaf_rn(__fmul_rn(mg, mg), (W), t2);                           \
    } while (0)

        #pragma unroll 4
        for (int g = 0; g < 16; ++g) {
            uint4  n4 = neP[g];
            float4 G4 = GP[g];
            float4 W4 = wP[g];
            PROC(n4.x, G4.x, W4.x);
            PROC(n4.y, G4.y, W4.y);
            PROC(n4.z, G4.z, W4.z);
            PROC(n4.w, G4.w, W4.w);
        }
#undef PROC

        float base = s_WB2[p] + t2;
        s_loss[j * TP_ + p]        = base + t1;
        s_loss[(j + 33) * TP_ + p] = base + __uint_as_float(__float_as_uint(t1) ^ flip);
    }
    // candidate 32 (= ori): v = cos_sn/8, same factored form
    if (warp == 7) {
        const int p = lane & 7, chunk = lane >> 3;
        const int sb = chunk * 16;
        float t1 = 0.f, t2 = 0.f;
        #pragma unroll
        for (int s = sb; s < sb + 16; ++s) {
            float v = s_csT[p][s] * 0.125f;
            t1 = __fmaf_rn(v, s_G[p][s], t1);
            t2 = __fmaf_rn(__fmul_rn(v, v), s_w[s], t2);
        }
        s_p32[chunk][p] = t1 + t2;
    }
    __syncthreads();

    // ---- phase 5: warp p argmin over 65 (lexicographic shuffle-min) ----
    {
        const int p = warp;
        float va = s_loss[lane * TP_ + p];
        float vb = s_loss[(lane + 33) * TP_ + p];
        float v = va; int ci = lane;
        if (vb < v) { v = vb; ci = lane + 33; }
        if (lane == 0) {
            float v32 = s_WB2[p] +
                ((((s_p32[0][p] + s_p32[1][p]) + s_p32[2][p]) + s_p32[3][p]));
            s_loss[32 * TP_ + p] = v32;
            if (v32 < v || (v32 == v && 32 < ci)) { v = v32; ci = 32; }
        }
        #pragma unroll
        for (int off = 16; off; off >>= 1) {
            float v2 = __shfl_xor_sync(0xFFFFFFFFu, v, off);
            int   c2 = __shfl_xor_sync(0xFFFFFFFFu, ci, off);
            if (v2 < v || (v2 == v && c2 < ci)) { v = v2; ci = c2; }
        }
        if (lane == 0) {
            float rp = s_rv[p];
            int rank = 0;
            #pragma unroll
            for (int q = 0; q < TP_; ++q)
                rank += (s_rv[q] < rp) || (s_rv[q] == rp && q < p);
            int idx = (rank < CUR_TP_ && s_sel) ? ci : 32;
            out[t * TP_ + p] = (float)s_clv[idx * TP_ + p];
            s_rl[p] = s_loss[idx * TP_ + p];
        }
    }
    __syncthreads();
    if (tid == 0) {
        float rl = 0.f;
        #pragma unroll
        for (int p = 0; p < TP_; ++p) rl = __fadd_rn(rl, s_rl[p]);
        out[T_ * TP_ + t] = rl * 0.125f;
    }
}

extern "C" void kernel_launch(void* const* d_in, const int* in_sizes, int n_in,
                              void* d_out, int out_size) {
    (void)in_sizes; (void)n_in; (void)out_size;
    detect_dtype_kernel<<<1, 1>>>(d_in[0]);
    fused_kernel<<<T_, 256>>>(
        d_in[0], d_in[1], d_in[2],
        (const float*)d_in[3], (const float*)d_in[4], (const float*)d_in[5],
        (const float*)d_in[6], (const float*)d_in[7],
        (float*)d_out);
}

// round 9
// speedup vs baseline: 1.2737x; 1.0784x over previous
#include <cuda_runtime.h>

// CritiGraph_64175401337324 — fused kernel v5:
//  = R6 body exactly (grid 1024, bounds(256,5), factored loss, butterfly)
//  + phase-4 I2F eliminated via magic-constant int->float (bit-exact).

namespace {
constexpr int T_   = 1024;
constexpr int S_   = 64;
constexpr int D_   = 256;
constexpr int TP_  = 8;
constexpr int C_   = 65;
constexpr int CUR_TP_ = 4;
}

__device__ int g_is64;

__global__ void detect_dtype_kernel(const void* p0) {
    // int64 values in [-131071,131071] => high half == sign-ext of low half
    const long long* p = (const long long*)p0;
    int ok = 1;
    for (int i = 0; i < 64; ++i) {
        long long v = p[i];
        int lo = (int)v, hi = (int)(v >> 32);
        if (hi != (lo < 0 ? -1 : 0)) { ok = 0; break; }
    }
    g_is64 = ok;
}

// pack |v| with sign in bit 31
__device__ __forceinline__ unsigned enc_loc(int v) {
    unsigned a = (unsigned)(v < 0 ? -v : v);
    if (v < 0) a |= 0x80000000u;
    return a;
}

// sign * (16 - e), e = frexp-exponent of ((|a|^|b|)+1). Exact in fp32.
__device__ __forceinline__ float cos_core(unsigned ea, unsigned eb) {
    unsigned u = ea ^ eb;
    int e = 32 - __clz((int)((u & 0x7FFFFFFFu) + 1u));
    float f = (float)(16 - e);
    return (u & 0x80000000u) ? -f : f;
}

__global__ void __launch_bounds__(256, 5) fused_kernel(
    const void*  __restrict__ sta_loc,
    const void*  __restrict__ nei_loc,
    const void*  __restrict__ rand_numbers,
    const float* __restrict__ sta_emb,
    const float* __restrict__ nei_emb,
    const float* __restrict__ mask,
    const float* __restrict__ rand_vals,
    const float* __restrict__ t_rand,
    float* __restrict__ out)
{
    const int t    = blockIdx.x;
    const int tid  = threadIdx.x;
    const int lane = tid & 31;
    const int warp = tid >> 5;
    const int is64 = g_is64;
    const int p_ = tid & 7;
    const int j_ = tid >> 3;

    __shared__ __align__(16) float    s_eu[S_];
    __shared__ __align__(16) float    s_w[S_];          // |eu|*mask*invlth
    __shared__ __align__(16) float    s_m[S_];
    __shared__ __align__(16) float    s_csT[TP_][68];   // cos_sn, transposed
    __shared__ __align__(16) unsigned s_nlT[TP_][68];   // enc(nei), transposed
    __shared__ __align__(16) float    s_G[TP_][68];     // 2*w*B
    __shared__ float    s_WB2[TP_];                     // sum w*B^2
    __shared__ int      s_clv[C_ * TP_];
    __shared__ float    s_loss[C_ * TP_];
    __shared__ float    s_p32[4][TP_];
    __shared__ float    s_rv[TP_], s_rl[TP_];
    __shared__ float    s_red[2];
    __shared__ int      s_sel;

    // ---- issue nei batch-1 loads first (in flight during integer work) ----
    const float4* st4 = (const float4*)(sta_emb + (size_t)t * D_);
    const float4  ua  = st4[lane];
    const float4  ub  = st4[lane + 32];
    const float4* nb  = (const float4*)(nei_emb + ((size_t)(t * S_ + warp * 8)) * D_);

    float4 A[4], Bv[4];
    #pragma unroll
    for (int r = 0; r < 4; ++r) {
        A[r]  = nb[r * 64 + lane];
        Bv[r] = nb[r * 64 + lane + 32];
    }

    // ---- integer loads + encode (overlapped with nei latency) ----
    int nl0, nl1, rn, orip;
    if (is64) {
        const long long* NL = (const long long*)nei_loc + (size_t)t * (S_ * TP_);
        nl0  = (int)NL[tid];
        nl1  = (int)NL[tid + 256];
        rn   = (int)((const long long*)rand_numbers)[t * 256 + tid];
        orip = (int)((const long long*)sta_loc)[t * TP_ + p_];
    } else {
        const int* NL = (const int*)nei_loc + t * (S_ * TP_);
        nl0  = NL[tid];
        nl1  = NL[tid + 256];
        rn   = ((const int*)rand_numbers)[t * 256 + tid];
        orip = ((const int*)sta_loc)[t * TP_ + p_];
    }
    float m = 0.f;
    if (tid < S_) { m = mask[t * S_ + tid]; s_m[tid] = m; }
    if (tid < TP_) {
        s_rv[tid] = rand_vals[t * TP_ + tid];
        s_clv[32 * TP_ + tid] = orip;     // p_ == tid here
    }
    if (tid == 0) s_sel = (t_rand[t] < 0.8f) ? 1 : 0;

    {   // encodings + cos_sn (exact multiples of 1/16)
        const unsigned op = enc_loc(orip);
        unsigned ne0 = enc_loc(nl0);
        unsigned ne1 = enc_loc(nl1);
        s_nlT[p_][j_]      = ne0;
        s_nlT[p_][j_ + 32] = ne1;
        s_csT[p_][j_]      = cos_core(op, ne0) * 0.0625f;
        s_csT[p_][j_ + 32] = cos_core(op, ne1) * 0.0625f;
    }
    int vcand;
    {
        const int h = j_ >> 1;
        vcand = (orip ^ (1 << h)) ^ (rn & ((1 << h) - 1));
        s_clv[j_ * TP_ + p_]        = vcand;
        s_clv[(j_ + 33) * TP_ + p_] = -vcand;
    }
    // lth partial reduce (mask is 0/1: exact in any order)
    if (tid < S_) {
        float l = m;
        #pragma unroll
        for (int off = 16; off; off >>= 1) l += __shfl_xor_sync(0xFFFFFFFFu, l, off);
        if (lane == 0) s_red[warp] = l;
    }

    // ---- eu: FFMA batch-1, load batch-2, FFMA batch-2 ----
    float dot[8], nn[8];
    #pragma unroll
    for (int r = 0; r < 4; ++r) {
        dot[r] = A[r].x*ua.x + A[r].y*ua.y + A[r].z*ua.z + A[r].w*ua.w
               + Bv[r].x*ub.x + Bv[r].y*ub.y + Bv[r].z*ub.z + Bv[r].w*ub.w;
        nn[r]  = A[r].x*A[r].x + A[r].y*A[r].y + A[r].z*A[r].z + A[r].w*A[r].w
               + Bv[r].x*Bv[r].x + Bv[r].y*Bv[r].y + Bv[r].z*Bv[r].z + Bv[r].w*Bv[r].w;
    }
    #pragma unroll
    for (int r = 0; r < 4; ++r) {
        A[r]  = nb[(4 + r) * 64 + lane];
        Bv[r] = nb[(4 + r) * 64 + lane + 32];
    }
    #pragma unroll
    for (int r = 0; r < 4; ++r) {
        dot[4+r] = A[r].x*ua.x + A[r].y*ua.y + A[r].z*ua.z + A[r].w*ua.w
                 + Bv[r].x*ub.x + Bv[r].y*ub.y + Bv[r].z*ub.z + Bv[r].w*ub.w;
        nn[4+r]  = A[r].x*A[r].x + A[r].y*A[r].y + A[r].z*A[r].z + A[r].w*A[r].w
                 + Bv[r].x*Bv[r].x + Bv[r].y*Bv[r].y + Bv[r].z*Bv[r].z + Bv[r].w*Bv[r].w;
    }
    float ss = ua.x*ua.x + ua.y*ua.y + ua.z*ua.z + ua.w*ua.w
             + ub.x*ub.x + ub.y*ub.y + ub.z*ub.z + ub.w*ub.w;

    // ---- merged butterfly: 16 values reduced in 31 shuffles (same FP tree) ----
    {
        float r16[16];
        #pragma unroll
        for (int i = 0; i < 8; ++i) { r16[i] = dot[i]; r16[8+i] = nn[i]; }
        float t0[16];
        #pragma unroll
        for (int i = 0; i < 16; ++i)
            t0[i] = r16[i] + __shfl_xor_sync(0xFFFFFFFFu, r16[i], 16);
        float m8[8];
        #pragma unroll
        for (int k = 0; k < 8; ++k) m8[k] = (lane & 16) ? t0[k+8] : t0[k];
        float u4[8];
        #pragma unroll
        for (int k = 0; k < 8; ++k)
            u4[k] = m8[k] + __shfl_xor_sync(0xFFFFFFFFu, m8[k], 8);
        float q[4];
        #pragma unroll
        for (int k = 0; k < 4; ++k) q[k] = (lane & 8) ? u4[k+4] : u4[k];
        float v4[4];
        #pragma unroll
        for (int k = 0; k < 4; ++k)
            v4[k] = q[k] + __shfl_xor_sync(0xFFFFFFFFu, q[k], 4);
        float w0 = (lane & 4) ? v4[2] : v4[0];
        float w1 = (lane & 4) ? v4[3] : v4[1];
        float x0 = w0 + __shfl_xor_sync(0xFFFFFFFFu, w0, 2);
        float x1 = w1 + __shfl_xor_sync(0xFFFFFFFFu, w1, 2);
        float y  = (lane & 2) ? x1 : x0;
        float z  = y + __shfl_xor_sync(0xFFFFFFFFu, y, 1);
        #pragma unroll
        for (int off = 16; off; off >>= 1) ss += __shfl_xor_sync(0xFFFFFFFFu, ss, off);
        float nnv = __shfl_xor_sync(0xFFFFFFFFu, z, 16);   // nn for same row
        if (lane < 16 && !(lane & 1)) {
            int row = lane >> 1;
            s_eu[warp * 8 + row] = z / (sqrtf(ss) * sqrtf(nnv));
        }
    }
    __syncthreads();                     // s_eu, s_red, s_csT, s_nlT, s_m ready

    // ---- B-phase: warp = p, lanes cover s and s+32 ----
    {
        const float invlth = __frcp_rn(s_red[0] + s_red[1] + 1e-12f);
        const int p = warp, s0 = lane, s1 = lane + 32;
        float sum0 = 0.f, sum1 = 0.f;
        #pragma unroll
        for (int pp = 0; pp < TP_; ++pp) { sum0 += s_csT[pp][s0]; sum1 += s_csT[pp][s1]; }
        float cs0 = s_csT[p][s0], cs1 = s_csT[p][s1];
        float eu0 = s_eu[s0],     eu1 = s_eu[s1];
        float B0 = (sum0 - cs0) * 0.125f - eu0;            // exact A8, 1 rounding
        float B1 = (sum1 - cs1) * 0.125f - eu1;
        float w0 = fabsf(eu0) * s_m[s0] * invlth;
        float w1 = fabsf(eu1) * s_m[s1] * invlth;
        float q0 = w0 * B0, q1 = w1 * B1;
        s_G[p][s0] = q0 + q0;                              // 2wB (exact x2)
        s_G[p][s1] = q1 + q1;
        if (p == 0) { s_w[s0] = w0; s_w[s1] = w1; }
        float wb2 = __fmaf_rn(q1, B1, q0 * B0);
        #pragma unroll
        for (int off = 16; off; off >>= 1) wb2 += __shfl_xor_sync(0xFFFFFFFFu, wb2, off);
        if (lane == 0) s_WB2[p] = wb2;
    }
    __syncthreads();

    // ---- phase 4: pair (j, j+33); no I2F — magic-constant float(clz) ----
    {
        const int p = p_, j = j_;
        const unsigned e0 = enc_loc(vcand);
        const unsigned flip = e0 ? 0x80000000u : 0u;

        const uint4*  neP = (const uint4*) &s_nlT[p][0];
        const float4* GP  = (const float4*)&s_G[p][0];
        const float4* wP  = (const float4*)s_w;

        float t1 = 0.f, t2 = 0.f;

        // mg = (clz(x2)-15)/128, computed bit-exactly without I2F:
        // f' = int_as_float(0x4B000000|clz) = 2^23 + clz (exact);
        // mg = fma(f', 1/128, -(2^23+15)/128) — product is exponent shift
        // (exact), constant exactly representable, one rounding to an exact
        // multiple of 2^-7 => identical bits to the I2F version.
#define PROC(NE, G, W) do {                                                   \
        unsigned u  = e0 ^ (NE);                                              \
        unsigned x2 = u * 2u + 2u;                                            \
        float fc = __int_as_float(0x4B000000 | __clz((int)x2));               \
        float mg = __fmaf_rn(fc, 0.0078125f, -65536.1171875f);                \
        float sG = __uint_as_float(__float_as_uint(G) ^ (u & 0x80000000u));   \
        t1 = __fmaf_rn(mg, sG, t1);                                           \
        t2 = __fmaf_rn(__fmul_rn(mg, mg), (W), t2);                           \
    } while (0)

        #pragma unroll 4
        for (int g = 0; g < 16; ++g) {
            uint4  n4 = neP[g];
            float4 G4 = GP[g];
            float4 W4 = wP[g];
            PROC(n4.x, G4.x, W4.x);
            PROC(n4.y, G4.y, W4.y);
            PROC(n4.z, G4.z, W4.z);
            PROC(n4.w, G4.w, W4.w);
        }
#undef PROC

        float base = s_WB2[p] + t2;
        s_loss[j * TP_ + p]        = base + t1;
        s_loss[(j + 33) * TP_ + p] = base + __uint_as_float(__float_as_uint(t1) ^ flip);
    }
    // candidate 32 (= ori): v = cos_sn/8, same factored form
    if (warp == 7) {
        const int p = lane & 7, chunk = lane >> 3;
        const int sb = chunk * 16;
        float t1 = 0.f, t2 = 0.f;
        #pragma unroll
        for (int s = sb; s < sb + 16; ++s) {
            float v = s_csT[p][s] * 0.125f;
            t1 = __fmaf_rn(v, s_G[p][s], t1);
            t2 = __fmaf_rn(__fmul_rn(v, v), s_w[s], t2);
        }
        s_p32[chunk][p] = t1 + t2;
    }
    __syncthreads();

    // ---- phase 5: warp p argmin over 65 (lexicographic shuffle-min) ----
    {
        const int p = warp;
        float va = s_loss[lane * TP_ + p];
        float vb = s_loss[(lane + 33) * TP_ + p];
        float v = va; int ci = lane;
        if (vb < v) { v = vb; ci = lane + 33; }
        if (lane == 0) {
            float v32 = s_WB2[p] +
                ((((s_p32[0][p] + s_p32[1][p]) + s_p32[2][p]) + s_p32[3][p]));
            s_loss[32 * TP_ + p] = v32;
            if (v32 < v || (v32 == v && 32 < ci)) { v = v32; ci = 32; }
        }
        #pragma unroll
        for (int off = 16; off; off >>= 1) {
            float v2 = __shfl_xor_sync(0xFFFFFFFFu, v, off);
            int   c2 = __shfl_xor_sync(0xFFFFFFFFu, ci, off);
            if (v2 < v || (v2 == v && c2 < ci)) { v = v2; ci = c2; }
        }
        if (lane == 0) {
            float rp = s_rv[p];
            int rank = 0;
            #pragma unroll
            for (int q = 0; q < TP_; ++q)
                rank += (s_rv[q] < rp) || (s_rv[q] == rp && q < p);
            int idx = (rank < CUR_TP_ && s_sel) ? ci : 32;
            out[t * TP_ + p] = (float)s_clv[idx * TP_ + p];
            s_rl[p] = s_loss[idx * TP_ + p];
        }
    }
    __syncthreads();
    if (tid == 0) {
        float rl = 0.f;
        #pragma unroll
        for (int p = 0; p < TP_; ++p) rl = __fadd_rn(rl, s_rl[p]);
        out[T_ * TP_ + t] = rl * 0.125f;
    }
}

extern "C" void kernel_launch(void* const* d_in, const int* in_sizes, int n_in,
                              void* d_out, int out_size) {
    (void)in_sizes; (void)n_in; (void)out_size;
    detect_dtype_kernel<<<1, 1>>>(d_in[0]);
    fused_kernel<<<T_, 256>>>(
        d_in[0], d_in[1], d_in[2],
        (const float*)d_in[3], (const float*)d_in[4], (const float*)d_in[5],
        (const float*)d_in[6], (const float*)d_in[7],
        (float*)d_out);
}

// round 10
// speedup vs baseline: 1.3116x; 1.0297x over previous
#include <cuda_runtime.h>

// CritiGraph_64175401337324 — fused kernel v6:
//  = R6/v5 body (grid 1024, bounds(256,5), factored loss, butterfly)
//  + dtype detection inlined per-warp (detect kernel & graph node removed)
//  + bfind-direct magic float(clz) (bit-exact, one fewer ALU op)
//  + phase-4 unroll 8

namespace {
constexpr int T_   = 1024;
constexpr int S_   = 64;
constexpr int D_   = 256;
constexpr int TP_  = 8;
constexpr int C_   = 65;
constexpr int CUR_TP_ = 4;
}

// pack |v| with sign in bit 31
__device__ __forceinline__ unsigned enc_loc(int v) {
    unsigned a = (unsigned)(v < 0 ? -v : v);
    if (v < 0) a |= 0x80000000u;
    return a;
}

// sign * (16 - e), e = frexp-exponent of ((|a|^|b|)+1). Exact in fp32.
__device__ __forceinline__ float cos_core(unsigned ea, unsigned eb) {
    unsigned u = ea ^ eb;
    int e = 32 - __clz((int)((u & 0x7FFFFFFFu) + 1u));
    float f = (float)(16 - e);
    return (u & 0x80000000u) ? -f : f;
}

__device__ __forceinline__ unsigned bfind_u32(unsigned x) {
    unsigned r;
    asm("bfind.u32 %0, %1;" : "=r"(r) : "r"(x));
    return r;                              // = 31 - clz(x), x != 0
}

__global__ void __launch_bounds__(256, 5) fused_kernel(
    const void*  __restrict__ sta_loc,
    const void*  __restrict__ nei_loc,
    const void*  __restrict__ rand_numbers,
    const float* __restrict__ sta_emb,
    const float* __restrict__ nei_emb,
    const float* __restrict__ mask,
    const float* __restrict__ rand_vals,
    const float* __restrict__ t_rand,
    float* __restrict__ out)
{
    const int t    = blockIdx.x;
    const int tid  = threadIdx.x;
    const int lane = tid & 31;
    const int warp = tid >> 5;
    const int p_ = tid & 7;
    const int j_ = tid >> 3;

    __shared__ __align__(16) float    s_eu[S_];
    __shared__ __align__(16) float    s_w[S_];          // |eu|*mask*invlth
    __shared__ __align__(16) float    s_m[S_];
    __shared__ __align__(16) float    s_csT[TP_][68];   // cos_sn, transposed
    __shared__ __align__(16) unsigned s_nlT[TP_][68];   // enc(nei), transposed
    __shared__ __align__(16) float    s_G[TP_][68];     // 2*w*B
    __shared__ float    s_WB2[TP_];                     // sum w*B^2
    __shared__ int      s_clv[C_ * TP_];
    __shared__ float    s_loss[C_ * TP_];
    __shared__ float    s_p32[4][TP_];
    __shared__ float    s_rv[TP_], s_rl[TP_];
    __shared__ float    s_red[2];
    __shared__ int      s_sel;

    // ---- issue nei batch-1 loads first (in flight during everything) ----
    const float4* st4 = (const float4*)(sta_emb + (size_t)t * D_);
    const float4  ua  = st4[lane];
    const float4  ub  = st4[lane + 32];
    const float4* nb  = (const float4*)(nei_emb + ((size_t)(t * S_ + warp * 8)) * D_);

    float4 A[4], Bv[4];
    #pragma unroll
    for (int r = 0; r < 4; ++r) {
        A[r]  = nb[r * 64 + lane];
        Bv[r] = nb[r * 64 + lane + 32];
    }

    // ---- per-warp dtype detection (no extra kernel, no cross-warp sync) ----
    // int64 values in [-131071,131071] => each 8-byte word's high half is the
    // sign extension of its low half. 64 words sampled (2 per lane), same
    // region for all CTAs (stays hot in L2/L1).
    int is64;
    {
        const long long* pw = (const long long*)sta_loc;
        long long v0 = pw[lane * 2];
        long long v1 = pw[lane * 2 + 1];
        int lo0 = (int)v0, hi0 = (int)(v0 >> 32);
        int lo1 = (int)v1, hi1 = (int)(v1 >> 32);
        int ok = (hi0 == (lo0 >> 31)) && (hi1 == (lo1 >> 31));
        is64 = (__ballot_sync(0xFFFFFFFFu, ok) == 0xFFFFFFFFu);
    }

    // ---- integer loads + encode (overlapped with nei latency) ----
    int nl0, nl1, rn, orip;
    if (is64) {
        const long long* NL = (const long long*)nei_loc + (size_t)t * (S_ * TP_);
        nl0  = (int)NL[tid];
        nl1  = (int)NL[tid + 256];
        rn   = (int)((const long long*)rand_numbers)[t * 256 + tid];
        orip = (int)((const long long*)sta_loc)[t * TP_ + p_];
    } else {
        const int* NL = (const int*)nei_loc + t * (S_ * TP_);
        nl0  = NL[tid];
        nl1  = NL[tid + 256];
        rn   = ((const int*)rand_numbers)[t * 256 + tid];
        orip = ((const int*)sta_loc)[t * TP_ + p_];
    }
    float m = 0.f;
    if (tid < S_) { m = mask[t * S_ + tid]; s_m[tid] = m; }
    if (tid < TP_) {
        s_rv[tid] = rand_vals[t * TP_ + tid];
        s_clv[32 * TP_ + tid] = orip;     // p_ == tid here
    }
    if (tid == 0) s_sel = (t_rand[t] < 0.8f) ? 1 : 0;

    {   // encodings + cos_sn (exact multiples of 1/16)
        const unsigned op = enc_loc(orip);
        unsigned ne0 = enc_loc(nl0);
        unsigned ne1 = enc_loc(nl1);
        s_nlT[p_][j_]      = ne0;
        s_nlT[p_][j_ + 32] = ne1;
        s_csT[p_][j_]      = cos_core(op, ne0) * 0.0625f;
        s_csT[p_][j_ + 32] = cos_core(op, ne1) * 0.0625f;
    }
    int vcand;
    {
        const int h = j_ >> 1;
        vcand = (orip ^ (1 << h)) ^ (rn & ((1 << h) - 1));
        s_clv[j_ * TP_ + p_]        = vcand;
        s_clv[(j_ + 33) * TP_ + p_] = -vcand;
    }
    // lth partial reduce (mask is 0/1: exact in any order)
    if (tid < S_) {
        float l = m;
        #pragma unroll
        for (int off = 16; off; off >>= 1) l += __shfl_xor_sync(0xFFFFFFFFu, l, off);
        if (lane == 0) s_red[warp] = l;
    }

    // ---- eu: FFMA batch-1, load batch-2, FFMA batch-2 ----
    float dot[8], nn[8];
    #pragma unroll
    for (int r = 0; r < 4; ++r) {
        dot[r] = A[r].x*ua.x + A[r].y*ua.y + A[r].z*ua.z + A[r].w*ua.w
               + Bv[r].x*ub.x + Bv[r].y*ub.y + Bv[r].z*ub.z + Bv[r].w*ub.w;
        nn[r]  = A[r].x*A[r].x + A[r].y*A[r].y + A[r].z*A[r].z + A[r].w*A[r].w
               + Bv[r].x*Bv[r].x + Bv[r].y*Bv[r].y + Bv[r].z*Bv[r].z + Bv[r].w*Bv[r].w;
    }
    #pragma unroll
    for (int r = 0; r < 4; ++r) {
        A[r]  = nb[(4 + r) * 64 + lane];
        Bv[r] = nb[(4 + r) * 64 + lane + 32];
    }
    #pragma unroll
    for (int r = 0; r < 4; ++r) {
        dot[4+r] = A[r].x*ua.x + A[r].y*ua.y + A[r].z*ua.z + A[r].w*ua.w
                 + Bv[r].x*ub.x + Bv[r].y*ub.y + Bv[r].z*ub.z + Bv[r].w*ub.w;
        nn[4+r]  = A[r].x*A[r].x + A[r].y*A[r].y + A[r].z*A[r].z + A[r].w*A[r].w
                 + Bv[r].x*Bv[r].x + Bv[r].y*Bv[r].y + Bv[r].z*Bv[r].z + Bv[r].w*Bv[r].w;
    }
    float ss = ua.x*ua.x + ua.y*ua.y + ua.z*ua.z + ua.w*ua.w
             + ub.x*ub.x + ub.y*ub.y + ub.z*ub.z + ub.w*ub.w;

    // ---- merged butterfly: 16 values reduced in 31 shuffles (same FP tree) ----
    {
        float r16[16];
        #pragma unroll
        for (int i = 0; i < 8; ++i) { r16[i] = dot[i]; r16[8+i] = nn[i]; }
        float t0[16];
        #pragma unroll
        for (int i = 0; i < 16; ++i)
            t0[i] = r16[i] + __shfl_xor_sync(0xFFFFFFFFu, r16[i], 16);
        float m8[8];
        #pragma unroll
        for (int k = 0; k < 8; ++k) m8[k] = (lane & 16) ? t0[k+8] : t0[k];
        float u4[8];
        #pragma unroll
        for (int k = 0; k < 8; ++k)
            u4[k] = m8[k] + __shfl_xor_sync(0xFFFFFFFFu, m8[k], 8);
        float q[4];
        #pragma unroll
        for (int k = 0; k < 4; ++k) q[k] = (lane & 8) ? u4[k+4] : u4[k];
        float v4[4];
        #pragma unroll
        for (int k = 0; k < 4; ++k)
            v4[k] = q[k] + __shfl_xor_sync(0xFFFFFFFFu, q[k], 4);
        float w0 = (lane & 4) ? v4[2] : v4[0];
        float w1 = (lane & 4) ? v4[3] : v4[1];
        float x0 = w0 + __shfl_xor_sync(0xFFFFFFFFu, w0, 2);
        float x1 = w1 + __shfl_xor_sync(0xFFFFFFFFu, w1, 2);
        float y  = (lane & 2) ? x1 : x0;
        float z  = y + __shfl_xor_sync(0xFFFFFFFFu, y, 1);
        #pragma unroll
        for (int off = 16; off; off >>= 1) ss += __shfl_xor_sync(0xFFFFFFFFu, ss, off);
        float nnv = __shfl_xor_sync(0xFFFFFFFFu, z, 16);   // nn for same row
        if (lane < 16 && !(lane & 1)) {
            int row = lane >> 1;
            s_eu[warp * 8 + row] = z / (sqrtf(ss) * sqrtf(nnv));
        }
    }
    __syncthreads();                     // s_eu, s_red, s_csT, s_nlT, s_m ready

    // ---- B-phase: warp = p, lanes cover s and s+32 ----
    {
        const float invlth = __frcp_rn(s_red[0] + s_red[1] + 1e-12f);
        const int p = warp, s0 = lane, s1 = lane + 32;
        float sum0 = 0.f, sum1 = 0.f;
        #pragma unroll
        for (int pp = 0; pp < TP_; ++pp) { sum0 += s_csT[pp][s0]; sum1 += s_csT[pp][s1]; }
        float cs0 = s_csT[p][s0], cs1 = s_csT[p][s1];
        float eu0 = s_eu[s0],     eu1 = s_eu[s1];
        float B0 = (sum0 - cs0) * 0.125f - eu0;            // exact A8, 1 rounding
        float B1 = (sum1 - cs1) * 0.125f - eu1;
        float w0 = fabsf(eu0) * s_m[s0] * invlth;
        float w1 = fabsf(eu1) * s_m[s1] * invlth;
        float q0 = w0 * B0, q1 = w1 * B1;
        s_G[p][s0] = q0 + q0;                              // 2wB (exact x2)
        s_G[p][s1] = q1 + q1;
        if (p == 0) { s_w[s0] = w0; s_w[s1] = w1; }
        float wb2 = __fmaf_rn(q1, B1, q0 * B0);
        #pragma unroll
        for (int off = 16; off; off >>= 1) wb2 += __shfl_xor_sync(0xFFFFFFFFu, wb2, off);
        if (lane == 0) s_WB2[p] = wb2;
    }
    __syncthreads();

    // ---- phase 4: pair (j, j+33); bfind-direct magic float(clz) ----
    {
        const int p = p_, j = j_;
        const unsigned e0 = enc_loc(vcand);
        const unsigned flip = e0 ? 0x80000000u : 0u;

        const uint4*  neP = (const uint4*) &s_nlT[p][0];
        const float4* GP  = (const float4*)&s_G[p][0];
        const float4* wP  = (const float4*)s_w;

        float t1 = 0.f, t2 = 0.f;

        // mg = (clz(x2)-15)/128 = (16-bfind(x2))/128 computed bit-exactly:
        // fc = int_as_float(0x4B000000|bfind) = 2^23+bfind (exact);
        // mg = fma(fc, -1/128, (2^23+16)/128) — product is an exponent shift
        // (exact), constant 65536.125f exact, one rounding to an exact
        // multiple of 2^-7 => identical bits to the I2F/clz version.
#define PROC(NE, G, W) do {                                                   \
        unsigned u  = e0 ^ (NE);                                              \
        unsigned x2 = u * 2u + 2u;                                            \
        float fc = __uint_as_float(0x4B000000u | bfind_u32(x2));              \
        float mg = __fmaf_rn(fc, -0.0078125f, 65536.125f);                    \
        float sG = __uint_as_float(__float_as_uint(G) ^ (u & 0x80000000u));   \
        t1 = __fmaf_rn(mg, sG, t1);                                           \
        t2 = __fmaf_rn(__fmul_rn(mg, mg), (W), t2);                           \
    } while (0)

        #pragma unroll 8
        for (int g = 0; g < 16; ++g) {
            uint4  n4 = neP[g];
            float4 G4 = GP[g];
            float4 W4 = wP[g];
            PROC(n4.x, G4.x, W4.x);
            PROC(n4.y, G4.y, W4.y);
            PROC(n4.z, G4.z, W4.z);
            PROC(n4.w, G4.w, W4.w);
        }
#undef PROC

        float base = s_WB2[p] + t2;
        s_loss[j * TP_ + p]        = base + t1;
        s_loss[(j + 33) * TP_ + p] = base + __uint_as_float(__float_as_uint(t1) ^ flip);
    }
    // candidate 32 (= ori): v = cos_sn/8, same factored form
    if (warp == 7) {
        const int p = lane & 7, chunk = lane >> 3;
        const int sb = chunk * 16;
        float t1 = 0.f, t2 = 0.f;
        #pragma unroll
        for (int s = sb; s < sb + 16; ++s) {
            float v = s_csT[p][s] * 0.125f;
            t1 = __fmaf_rn(v, s_G[p][s], t1);
            t2 = __fmaf_rn(__fmul_rn(v, v), s_w[s], t2);
        }
        s_p32[chunk][p] = t1 + t2;
    }
    __syncthreads();

    // ---- phase 5: warp p argmin over 65 (lexicographic shuffle-min) ----
    {
        const int p = warp;
        float va = s_loss[lane * TP_ + p];
        float vb = s_loss[(lane + 33) * TP_ + p];
        float v = va; int ci = lane;
        if (vb < v) { v = vb; ci = lane + 33; }
        if (lane == 0) {
            float v32 = s_WB2[p] +
                ((((s_p32[0][p] + s_p32[1][p]) + s_p32[2][p]) + s_p32[3][p]));
            s_loss[32 * TP_ + p] = v32;
            if (v32 < v || (v32 == v && 32 < ci)) { v = v32; ci = 32; }
        }
        #pragma unroll
        for (int off = 16; off; off >>= 1) {
            float v2 = __shfl_xor_sync(0xFFFFFFFFu, v, off);
            int   c2 = __shfl_xor_sync(0xFFFFFFFFu, ci, off);
            if (v2 < v || (v2 == v && c2 < ci)) { v = v2; ci = c2; }
        }
        if (lane == 0) {
            float rp = s_rv[p];
            int rank = 0;
            #pragma unroll
            for (int q = 0; q < TP_; ++q)
                rank += (s_rv[q] < rp) || (s_rv[q] == rp && q < p);
            int idx = (rank < CUR_TP_ && s_sel) ? ci : 32;
            out[t * TP_ + p] = (float)s_clv[idx * TP_ + p];
            s_rl[p] = s_loss[idx * TP_ + p];
        }
    }
    __syncthreads();
    if (tid == 0) {
        float rl = 0.f;
        #pragma unroll
        for (int p = 0; p < TP_; ++p) rl = __fadd_rn(rl, s_rl[p]);
        out[T_ * TP_ + t] = rl * 0.125f;
    }
}

extern "C" void kernel_launch(void* const* d_in, const int* in_sizes, int n_in,
                              void* d_out, int out_size) {
    (void)in_sizes; (void)n_in; (void)out_size;
    fused_kernel<<<T_, 256>>>(
        d_in[0], d_in[1], d_in[2],
        (const float*)d_in[3], (const float*)d_in[4], (const float*)d_in[5],
        (const float*)d_in[6], (const float*)d_in[7],
        (float*)d_out);
}

// round 11
// speedup vs baseline: 1.3967x; 1.0649x over previous
#include <cuda_runtime.h>

// CritiGraph_64175401337324 — fused kernel v7 "decoupled warps":
// each warp owns 8 s-rows end-to-end (loads, eu, G, phase-4 partials for all
// candidates over its s-range). No __syncthreads until the final reduction.

namespace {
constexpr int T_   = 1024;
constexpr int S_   = 64;
constexpr int D_   = 256;
constexpr int TP_  = 8;
constexpr int C_   = 65;
constexpr int CUR_TP_ = 4;
}

// pack |v| with sign in bit 31
__device__ __forceinline__ unsigned enc_loc(int v) {
    unsigned a = (unsigned)(v < 0 ? -v : v);
    if (v < 0) a |= 0x80000000u;
    return a;
}

// sign * (16 - e), e = frexp-exponent of ((|a|^|b|)+1). Exact in fp32.
__device__ __forceinline__ float cos_core(unsigned ea, unsigned eb) {
    unsigned u = ea ^ eb;
    int e = 32 - __clz((int)((u & 0x7FFFFFFFu) + 1u));
    float f = (float)(16 - e);
    return (u & 0x80000000u) ? -f : f;
}

__device__ __forceinline__ unsigned bfind_u32(unsigned x) {
    unsigned r;
    asm("bfind.u32 %0, %1;" : "=r"(r) : "r"(x));
    return r;                              // = 31 - clz(x), x != 0
}

__global__ void __launch_bounds__(256, 4) fused_kernel(
    const void*  __restrict__ sta_loc,
    const void*  __restrict__ nei_loc,
    const void*  __restrict__ rand_numbers,
    const float* __restrict__ sta_emb,
    const float* __restrict__ nei_emb,
    const float* __restrict__ mask,
    const float* __restrict__ rand_vals,
    const float* __restrict__ t_rand,
    float* __restrict__ out)
{
    const int t    = blockIdx.x;
    const int tid  = threadIdx.x;
    const int lane = tid & 31;
    const int warp = tid >> 5;

    __shared__ __align__(16) unsigned sh_ne[TP_][72];   // warp-private [w][s*9+p]
    __shared__ __align__(16) float    sh_G[TP_][72];
    __shared__ float    sh_w[TP_][TP_];                 // [w][s_local]
    __shared__ float    sh_wb2[TP_][TP_];               // [w][p]
    __shared__ float    sP1[TP_ * 264];                 // [w][j(33)][p]
    __shared__ float    sP2[TP_ * 264];
    __shared__ float    s_loss[C_ * TP_];
    __shared__ float    s_rv[TP_], s_rl[TP_];
    __shared__ int      s_sel;

    // ================= phase A: all loads issued up front =================
    const float4* st4 = (const float4*)(sta_emb + (size_t)t * D_);
    const float4  ua  = st4[lane];
    const float4  ub  = st4[lane + 32];
    const float4* nb  = (const float4*)(nei_emb + ((size_t)(t * S_ + warp * 8)) * D_);

    float4 A[4], Bv[4];
    #pragma unroll
    for (int r = 0; r < 4; ++r) {
        A[r]  = nb[r * 64 + lane];
        Bv[r] = nb[r * 64 + lane + 32];
    }

    // dtype probes (same 64 leading words for every CTA -> cache-hot)
    const long long* pw = (const long long*)sta_loc;
    long long dv0 = pw[lane * 2];
    long long dv1 = pw[lane * 2 + 1];

    // nei_loc slice, speculative both-dtype loads (consecutive int32 pair)
    const int sl = lane >> 2;                // s_local 0..7
    const int p0 = (lane & 3) * 2;           // p pair {p0, p0+1}
    long long nlA = ((const long long*)nei_loc)[(size_t)t * 512 + warp * 64 + lane * 2];
    long long nlB = ((const long long*)nei_loc)[(size_t)t * 512 + warp * 64 + lane * 2 + 1];
    long long nl32 = ((const long long*)nei_loc)[(size_t)t * 256 + warp * 32 + lane];

    // sta_loc pair for (p0, p0+1)
    long long oA  = ((const long long*)sta_loc)[(size_t)t * 8 + p0];
    long long oB  = ((const long long*)sta_loc)[(size_t)t * 8 + p0 + 1];
    long long o32 = ((const long long*)sta_loc)[(size_t)t * 4 + (lane & 3)];

    float m_a   = mask[t * S_ + lane];
    float m_b   = mask[t * S_ + 32 + lane];
    float m_own = mask[t * S_ + warp * 8 + sl];

    if (tid < TP_) s_rv[tid] = rand_vals[t * TP_ + tid];
    if (tid == 0)  s_sel = (t_rand[t] < 0.8f) ? 1 : 0;

    // dtype decision (per warp, no cross-warp sync)
    int is64;
    {
        int lo0 = (int)dv0, hi0 = (int)(dv0 >> 32);
        int lo1 = (int)dv1, hi1 = (int)(dv1 >> 32);
        int ok = (hi0 == (lo0 >> 31)) && (hi1 == (lo1 >> 31));
        is64 = (__ballot_sync(0xFFFFFFFFu, ok) == 0xFFFFFFFFu);
    }

    int nl0, nl1, o0, o1;
    if (is64) {
        nl0 = (int)nlA; nl1 = (int)nlB;
        o0  = (int)oA;  o1  = (int)oB;
    } else {
        nl0 = (int)nl32; nl1 = (int)(nl32 >> 32);
        o0  = (int)o32;  o1  = (int)(o32 >> 32);
    }

    // per-warp lth (mask is 0/1: exact in any order)
    float invlth;
    {
        float l = m_a + m_b;
        #pragma unroll
        for (int off = 16; off; off >>= 1) l += __shfl_xor_sync(0xFFFFFFFFu, l, off);
        invlth = __frcp_rn(l + 1e-12f);
    }

    // encode + cos_sn + A8 (warp-local column sums over p)
    float A8_0, A8_1;
    {
        unsigned ne0 = enc_loc(nl0);
        unsigned ne1 = enc_loc(nl1);
        float cs0 = cos_core(enc_loc(o0), ne0) * 0.0625f;   // exact cos
        float cs1 = cos_core(enc_loc(o1), ne1) * 0.0625f;
        float c01 = cs0 + cs1;
        float c2  = c01 + __shfl_xor_sync(0xFFFFFFFFu, c01, 1);
        float sum8 = c2 + __shfl_xor_sync(0xFFFFFFFFu, c2, 2);  // sum over 8 p
        A8_0 = (sum8 - cs0) * 0.125f;
        A8_1 = (sum8 - cs1) * 0.125f;
        sh_ne[warp][sl * 9 + p0]     = ne0;
        sh_ne[warp][sl * 9 + p0 + 1] = ne1;
    }

    // ================= eu: FFMA batch-1, load batch-2, FFMA batch-2 =======
    float dot[8], nn[8];
    #pragma unroll
    for (int r = 0; r < 4; ++r) {
        dot[r] = A[r].x*ua.x + A[r].y*ua.y + A[r].z*ua.z + A[r].w*ua.w
               + Bv[r].x*ub.x + Bv[r].y*ub.y + Bv[r].z*ub.z + Bv[r].w*ub.w;
        nn[r]  = A[r].x*A[r].x + A[r].y*A[r].y + A[r].z*A[r].z + A[r].w*A[r].w
               + Bv[r].x*Bv[r].x + Bv[r].y*Bv[r].y + Bv[r].z*Bv[r].z + Bv[r].w*Bv[r].w;
    }
    #pragma unroll
    for (int r = 0; r < 4; ++r) {
        A[r]  = nb[(4 + r) * 64 + lane];
        Bv[r] = nb[(4 + r) * 64 + lane + 32];
    }
    #pragma unroll
    for (int r = 0; r < 4; ++r) {
        dot[4+r] = A[r].x*ua.x + A[r].y*ua.y + A[r].z*ua.z + A[r].w*ua.w
                 + Bv[r].x*ub.x + Bv[r].y*ub.y + Bv[r].z*ub.z + Bv[r].w*ub.w;
        nn[4+r]  = A[r].x*A[r].x + A[r].y*A[r].y + A[r].z*A[r].z + A[r].w*A[r].w
                 + Bv[r].x*Bv[r].x + Bv[r].y*Bv[r].y + Bv[r].z*Bv[r].z + Bv[r].w*Bv[r].w;
    }
    float ss = ua.x*ua.x + ua.y*ua.y + ua.z*ua.z + ua.w*ua.w
             + ub.x*ub.x + ub.y*ub.y + ub.z*ub.z + ub.w*ub.w;

    float euv;   // valid at lanes 2*row (row 0..7)
    {
        float r16[16];
        #pragma unroll
        for (int i = 0; i < 8; ++i) { r16[i] = dot[i]; r16[8+i] = nn[i]; }
        float t0[16];
        #pragma unroll
        for (int i = 0; i < 16; ++i)
            t0[i] = r16[i] + __shfl_xor_sync(0xFFFFFFFFu, r16[i], 16);
        float m8[8];
        #pragma unroll
        for (int k = 0; k < 8; ++k) m8[k] = (lane & 16) ? t0[k+8] : t0[k];
        float u4[8];
        #pragma unroll
        for (int k = 0; k < 8; ++k)
            u4[k] = m8[k] + __shfl_xor_sync(0xFFFFFFFFu, m8[k], 8);
        float q[4];
        #pragma unroll
        for (int k = 0; k < 4; ++k) q[k] = (lane & 8) ? u4[k+4] : u4[k];
        float v4[4];
        #pragma unroll
        for (int k = 0; k < 4; ++k)
            v4[k] = q[k] + __shfl_xor_sync(0xFFFFFFFFu, q[k], 4);
        float w0 = (lane & 4) ? v4[2] : v4[0];
        float w1 = (lane & 4) ? v4[3] : v4[1];
        float x0 = w0 + __shfl_xor_sync(0xFFFFFFFFu, w0, 2);
        float x1 = w1 + __shfl_xor_sync(0xFFFFFFFFu, w1, 2);
        float y  = (lane & 2) ? x1 : x0;
        float z  = y + __shfl_xor_sync(0xFFFFFFFFu, y, 1);
        #pragma unroll
        for (int off = 16; off; off >>= 1) ss += __shfl_xor_sync(0xFFFFFFFFu, ss, off);
        float nnv = __shfl_xor_sync(0xFFFFFFFFu, z, 16);
        euv = z / (sqrtf(ss) * sqrtf(nnv));   // meaningful at even lanes <16
    }

    // ================= G-prep (warp-local) =================
    {
        float eu_s = __shfl_sync(0xFFFFFFFFu, euv, sl * 2);
        float w_s  = fabsf(eu_s) * m_own * invlth;
        float B0 = A8_0 - eu_s;
        float B1 = A8_1 - eu_s;
        float q0 = w_s * B0, q1 = w_s * B1;
        sh_G[warp][sl * 9 + p0]     = q0 + q0;     // 2wB (exact x2)
        sh_G[warp][sl * 9 + p0 + 1] = q1 + q1;
        if ((lane & 3) == 0) sh_w[warp][sl] = w_s;
        float wb2_0 = q0 * B0;
        float wb2_1 = q1 * B1;
        #pragma unroll
        for (int off = 4; off <= 16; off <<= 1) {     // sum over 8 s-lanes
            wb2_0 += __shfl_xor_sync(0xFFFFFFFFu, wb2_0, off);
            wb2_1 += __shfl_xor_sync(0xFFFFFFFFu, wb2_1, off);
        }
        if (lane < 4) {
            sh_wb2[warp][2 * lane]     = wb2_0;
            sh_wb2[warp][2 * lane + 1] = wb2_1;
        }
    }
    __syncwarp();

    // ================= phase 4: per-warp partials over own 8 s =============
    {
        const int p  = lane & 7;
        const int jj = lane >> 3;

        unsigned ne_r[8];
        float    G_r[8], w_r[8];
        #pragma unroll
        for (int s = 0; s < 8; ++s) {
            ne_r[s] = sh_ne[warp][s * 9 + p];
            G_r[s]  = sh_G[warp][s * 9 + p];
            w_r[s]  = sh_w[warp][s];
        }
        const float wb2p = sh_wb2[warp][p];

        // prefetch candidate rn values (L1-hot after first warp) + ori[p]
        int rn_r[8], ori_p;
        if (is64) {
            const long long* R = (const long long*)rand_numbers + (size_t)t * 256;
            #pragma unroll
            for (int k = 0; k < 8; ++k) rn_r[k] = (int)R[(k * 4 + jj) * 8 + p];
            ori_p = (int)((const long long*)sta_loc)[(size_t)t * 8 + p];
        } else {
            const int* R = (const int*)rand_numbers + (size_t)t * 256;
            #pragma unroll
            for (int k = 0; k < 8; ++k) rn_r[k] = R[(k * 4 + jj) * 8 + p];
            ori_p = ((const int*)sta_loc)[(size_t)t * 8 + p];
        }
        const unsigned e0_32 = enc_loc(ori_p);

        #pragma unroll
        for (int step = 0; step < 9; ++step) {
            unsigned e0;
            int j;
            if (step < 8) {
                j = step * 4 + jj;
                int h = j >> 1;
                int vc = (ori_p ^ (1 << h)) ^ (rn_r[step] & ((1 << h) - 1));
                e0 = enc_loc(vc);
            } else {
                j = 32;
                e0 = e0_32;
            }
            float P1 = 0.f, P2 = wb2p;
            #pragma unroll
            for (int s = 0; s < 8; ++s) {
                unsigned u  = e0 ^ ne_r[s];
                unsigned x2 = u * 2u + 2u;
                float fc = __uint_as_float(0x4B000000u | bfind_u32(x2));
                float mg = __fmaf_rn(fc, -0.0078125f, 65536.125f);
                float sG = __uint_as_float(__float_as_uint(G_r[s]) ^ (u & 0x80000000u));
                P1 = __fmaf_rn(mg, sG, P1);
                P2 = __fmaf_rn(__fmul_rn(mg, mg), w_r[s], P2);
            }
            if (step < 8 || jj == 0) {
                int base = (warp * 33 + j) * 8 + p;
                sP1[base] = P1;
                sP2[base] = P2;
            }
        }
    }
    __syncthreads();

    // ================= phase 5a: reduce partials over warps ================
    {
        const int j_ = tid >> 3, p_ = tid & 7;
        float S1 = 0.f, S2 = 0.f;
        #pragma unroll
        for (int w = 0; w < 8; ++w) {
            S1 = __fadd_rn(S1, sP1[(w * 33 + j_) * 8 + p_]);
            S2 = __fadd_rn(S2, sP2[(w * 33 + j_) * 8 + p_]);
        }
        // flip bit: candidate value == 0 keeps '+' sign under negation
        int rnv = is64 ? (int)((const long long*)rand_numbers)[(size_t)t * 256 + j_ * 8 + p_]
                       : ((const int*)rand_numbers)[(size_t)t * 256 + j_ * 8 + p_];
        int orv = is64 ? (int)((const long long*)sta_loc)[(size_t)t * 8 + p_]
                       : ((const int*)sta_loc)[(size_t)t * 8 + p_];
        int h = j_ >> 1;
        int vc = (orv ^ (1 << h)) ^ (rnv & ((1 << h) - 1));
        unsigned flip = vc ? 0x80000000u : 0u;
        s_loss[j_ * 8 + p_]        = S2 + S1;
        s_loss[(j_ + 33) * 8 + p_] = S2 + __uint_as_float(__float_as_uint(S1) ^ flip);
        if (tid < TP_) {                     // candidate 32
            float T1 = 0.f, T2 = 0.f;
            #pragma unroll
            for (int w = 0; w < 8; ++w) {
                T1 = __fadd_rn(T1, sP1[(w * 33 + 32) * 8 + tid]);
                T2 = __fadd_rn(T2, sP2[(w * 33 + 32) * 8 + tid]);
            }
            s_loss[32 * 8 + tid] = T2 + T1;
        }
    }
    __syncthreads();

    // ================= phase 5b: warp p argmin + outputs ===================
    {
        const int p = warp;
        float va = s_loss[lane * 8 + p];
        float vb = s_loss[(lane + 33) * 8 + p];
        float v = va; int ci = lane;
        if (vb < v) { v = vb; ci = lane + 33; }
        if (lane == 0) {
            float v32 = s_loss[32 * 8 + p];
            if (v32 < v || (v32 == v && 32 < ci)) { v = v32; ci = 32; }
        }
        #pragma unroll
        for (int off = 16; off; off >>= 1) {
            float v2 = __shfl_xor_sync(0xFFFFFFFFu, v, off);
            int   c2 = __shfl_xor_sync(0xFFFFFFFFu, ci, off);
            if (v2 < v || (v2 == v && c2 < ci)) { v = v2; ci = c2; }
        }
        if (lane == 0) {
            float rp = s_rv[p];
            int rank = 0;
            #pragma unroll
            for (int q = 0; q < TP_; ++q)
                rank += (s_rv[q] < rp) || (s_rv[q] == rp && q < p);
            int idx = (rank < CUR_TP_ && s_sel) ? ci : 32;
            // recompute the selected candidate value
            int orv = is64 ? (int)((const long long*)sta_loc)[(size_t)t * 8 + p]
                           : ((const int*)sta_loc)[(size_t)t * 8 + p];
            int vv;
            if (idx == 32) {
                vv = orv;
            } else {
                int c = (idx < 32) ? idx : (idx - 33);
                int rnv = is64 ? (int)((const long long*)rand_numbers)[(size_t)t * 256 + c * 8 + p]
                               : ((const int*)rand_numbers)[(size_t)t * 256 + c * 8 + p];
                int h = c >> 1;
                vv = (orv ^ (1 << h)) ^ (rnv & ((1 << h) - 1));
                if (idx >= 33) vv = -vv;
            }
            out[t * TP_ + p] = (float)vv;
            s_rl[p] = s_loss[idx * 8 + p];
        }
    }
    __syncthreads();
    if (tid == 0) {
        float rl = 0.f;
        #pragma unroll
        for (int p = 0; p < TP_; ++p) rl = __fadd_rn(rl, s_rl[p]);
        out[T_ * TP_ + t] = rl * 0.125f;
    }
}

extern "C" void kernel_launch(void* const* d_in, const int* in_sizes, int n_in,
                              void* d_out, int out_size) {
    (void)in_sizes; (void)n_in; (void)out_size;
    fused_kernel<<<T_, 256>>>(
        d_in[0], d_in[1], d_in[2],
        (const float*)d_in[3], (const float*)d_in[4], (const float*)d_in[5],
        (const float*)d_in[6], (const float*)d_in[7],
        (float*)d_out);
}